// round 10
// baseline (speedup 1.0000x reference)
#include <cuda_runtime.h>
#include <cstdint>
#include <cstddef>

#define N_TFH 1000
#define N_TG  20000
#define N_E   4000000
#define NV    (N_E / 4)          // 1,000,000 float4 groups
#define N_TAB (N_TG + N_TFH)     // 21,000 table entries
#define GRID    148
#define THREADS 1024
#define SMEM_BYTES (N_TAB * 8)   // float2 table: 168,000 B

__device__ __forceinline__ float warp_reduce(float v) {
    #pragma unroll
    for (int o = 16; o > 0; o >>= 1)
        v += __shfl_xor_sync(0xFFFFFFFFu, v, o);
    return v;
}

// FFMA-pipe reciprocal: bit-magic seed + 2 Newton iterations (~1e-7 rel).
// No MUFU. Valid for positive normal x (here x in [0.01, ~70]).
__device__ __forceinline__ float fast_rcp(float x) {
    float r = __int_as_float(0x7EF311C3 - __float_as_int(x));
    r = r * fmaf(-x, r, 2.0f);
    r = r * fmaf(-x, r, 2.0f);
    return r;
}

// FFMA-pipe natural log (njuffa-style), ~1e-7 rel. No MUFU.
__device__ __forceinline__ float fast_logf(float a) {
    int e = (__float_as_int(a) - 0x3f2aaaab) & 0xff800000;
    float m = __int_as_float(__float_as_int(a) - e);   // m in [2/3, 4/3)
    float i = (float)e * 1.19209290e-7f;               // e * 2^-23
    float f = m - 1.0f;
    float s = f * f;
    float r = fmaf(0.230836749f, f, -0.279208571f);
    float t = fmaf(0.331826031f, f, -0.498910338f);
    r = fmaf(r, s, t);
    r = fmaf(r, s, f);
    r = fmaf(i, 0.693147182f, r);
    return r;
}

__global__ void zero_out_kernel(float* out) { out[0] = 0.0f; }

__global__ __launch_bounds__(THREADS, 1)
void fused_loss_kernel(
    const float* __restrict__ TF_high_mu,
    const float* __restrict__ TF_high_sigma,
    const float* __restrict__ TG_mu,
    const float* __restrict__ TG_sigma,
    const float* __restrict__ TF_high_exp,
    const float* __restrict__ TG_exp,
    const float4* __restrict__ k_edge,
    const float4* __restrict__ alpha,
    const float4* __restrict__ cov,
    const float4* __restrict__ edge_y,
    const float4* __restrict__ edge_x,
    const int*   __restrict__ father_num,
    const int4*  __restrict__ idx_tf_tg,
    const int4*  __restrict__ idx_tf_high,
    const int4*  __restrict__ edge_tg_idx,
    const int4*  __restrict__ is_high,
    float* __restrict__ out)
{
    extern __shared__ float2 s_tab[];   // (mu, sigma^2), fp32, 168 KB
    const float HALF_LOG2PI = 0.918938533204672742f;
    const int tid = threadIdx.x;

    // ---- build (mu, sig^2) table from coalesced reads ----
    for (int i = tid; i < N_TG; i += THREADS) {
        float sg = TG_sigma[i];
        s_tab[i] = make_float2(TG_mu[i], sg * sg);
    }
    for (int i = tid; i < N_TFH; i += THREADS) {
        float sg = TF_high_sigma[i];
        s_tab[N_TG + i] = make_float2(TF_high_mu[i], sg * sg);
    }
    __syncthreads();

    float acc = 0.0f;
    const int gtid   = blockIdx.x * THREADS + tid;
    const int stride = GRID * THREADS;

    // ---- p/q terms (21k elems total) ----
    if (gtid < N_TG) {
        float mu = TG_mu[gtid], sg = TG_sigma[gtid], x = TG_exp[gtid];
        float fn = (float)father_num[gtid];
        float z = (x - mu) / sg;
        float lp = -0.5f * z * z - fast_logf(sg) - HALF_LOG2PI;
        acc += (fn - 1.0f) * lp;                         // -q
    }
    if (gtid < N_TFH) {
        float mu = TF_high_mu[gtid], sg = TF_high_sigma[gtid], x = TF_high_exp[gtid];
        float z = (x - mu) / sg;
        acc += 0.5f * z * z + fast_logf(sg) + HALF_LOG2PI; // -p
    }

    // ---- edge term: MUFU-free inner loop ----
    for (int v = gtid; v < NV; v += stride) {
        float4 ke = k_edge[v];
        float4 al = alpha[v];
        float4 cv = cov[v];
        float4 ey = edge_y[v];
        float4 ex = edge_x[v];
        int4  itg = idx_tf_tg[v];
        int4  ith = idx_tf_high[v];
        int4  ieg = edge_tg_idx[v];
        int4  ih  = is_high[v];

        const float* kef = &ke.x; const float* alf = &al.x;
        const float* cvf = &cv.x; const float* eyf = &ey.x;
        const float* exf = &ex.x;
        const int* itgf = &itg.x; const int* ithf = &ith.x;
        const int* iegf = &ieg.x; const int* ihf  = &ih.x;

        #pragma unroll
        for (int l = 0; l < 4; l++) {
            int tfi = ihf[l] ? (N_TG + ithf[l]) : itgf[l];
            float2 tf = s_tab[tfi];          // (tf_mu, tf_sig^2)
            float2 tg = s_tab[iegf[l]];      // (tg_mu, tg_sig^2)

            float iv  = fast_rcp(tf.y);                       // 1/tf_sig^2
            float loc = fmaf(kef[l] * cvf[l], (eyf[l] - tf.x) * iv, tg.x);
            loc = fmaxf(loc, 0.0f) + 0.01f;
            float var = fmaf(-alf[l] * alf[l], iv, tg.y);
            var = fmaxf(var, 0.0f) + 0.01f;

            float dx = exf[l] - loc;
            // -logprob = 0.5*(dx^2/var + log(var)) + 0.5*log(2pi)
            acc += fmaf(0.5f, fmaf(dx * dx, fast_rcp(var), fast_logf(var)),
                        HALF_LOG2PI);
        }
    }

    // ---- block reduction -> one atomic per block ----
    acc = warp_reduce(acc);
    __shared__ float warp_sums[THREADS / 32];
    int lane = tid & 31, wid = tid >> 5;
    if (lane == 0) warp_sums[wid] = acc;
    __syncthreads();
    if (wid == 0) {
        float v = (lane < THREADS / 32) ? warp_sums[lane] : 0.0f;
        v = warp_reduce(v);
        if (lane == 0) atomicAdd(out, v);
    }
}

extern "C" void kernel_launch(void* const* d_in, const int* in_sizes, int n_in,
                              void* d_out, int out_size) {
    cudaFuncSetAttribute(fused_loss_kernel,
                         cudaFuncAttributeMaxDynamicSharedMemorySize, SMEM_BYTES);

    float* out = (float*)d_out;
    zero_out_kernel<<<1, 1>>>(out);

    fused_loss_kernel<<<GRID, THREADS, SMEM_BYTES>>>(
        (const float*)d_in[0], (const float*)d_in[1],
        (const float*)d_in[2], (const float*)d_in[3],
        (const float*)d_in[4], (const float*)d_in[5],
        (const float4*)d_in[6], (const float4*)d_in[7],
        (const float4*)d_in[8], (const float4*)d_in[9],
        (const float4*)d_in[10], (const int*)d_in[11],
        (const int4*)d_in[12], (const int4*)d_in[13],
        (const int4*)d_in[14], (const int4*)d_in[15],
        out);
}

// round 11
// speedup vs baseline: 1.0897x; 1.0897x over previous
#include <cuda_runtime.h>
#include <cstdint>
#include <cstddef>

#define N_TFH 1000
#define N_TG  20000
#define N_E   4000000
#define NV    (N_E / 4)          // 1,000,000 float4 groups
#define N_TAB (N_TG + N_TFH)     // 21,000
#define THREADS 256

// Precomputed gather tables (device global scratch — allowed by harness rules).
// g_tf_tab: (mu, 1/sigma^2); TG entries [0,N_TG), TF_high at [N_TG,N_TAB).
// g_tg_tab: (mu, sigma^2) for TG only.
__device__ float2 g_tf_tab[N_TAB];
__device__ float2 g_tg_tab[N_TG];

__device__ __forceinline__ float warp_reduce(float v) {
    #pragma unroll
    for (int o = 16; o > 0; o >>= 1)
        v += __shfl_xor_sync(0xFFFFFFFFu, v, o);
    return v;
}

// FFMA-pipe reciprocal: bit-magic seed + 2 Newton iterations. No MUFU.
__device__ __forceinline__ float fast_rcp(float x) {
    float r = __int_as_float(0x7EF311C3 - __float_as_int(x));
    r = r * fmaf(-x, r, 2.0f);
    r = r * fmaf(-x, r, 2.0f);
    return r;
}

// FFMA-pipe natural log (njuffa-style), ~1e-7 rel. No MUFU.
__device__ __forceinline__ float fast_logf(float a) {
    int e = (__float_as_int(a) - 0x3f2aaaab) & 0xff800000;
    float m = __int_as_float(__float_as_int(a) - e);   // m in [2/3, 4/3)
    float i = (float)e * 1.19209290e-7f;
    float f = m - 1.0f;
    float s = f * f;
    float r = fmaf(0.230836749f, f, -0.279208571f);
    float t = fmaf(0.331826031f, f, -0.498910338f);
    r = fmaf(r, s, t);
    r = fmaf(r, s, f);
    r = fmaf(i, 0.693147182f, r);
    return r;
}

// Prep: zero output, build gather tables (accurate division here, cost trivial).
__global__ void prep_kernel(const float* __restrict__ TF_high_mu,
                            const float* __restrict__ TF_high_sigma,
                            const float* __restrict__ TG_mu,
                            const float* __restrict__ TG_sigma,
                            float* out) {
    int i = blockIdx.x * blockDim.x + threadIdx.x;
    if (i == 0) out[0] = 0.0f;
    if (i < N_TG) {
        float mu = TG_mu[i], sg = TG_sigma[i];
        float s2 = sg * sg;
        g_tf_tab[i] = make_float2(mu, 1.0f / s2);
        g_tg_tab[i] = make_float2(mu, s2);
    }
    if (i < N_TFH) {
        float mu = TF_high_mu[i], sg = TF_high_sigma[i];
        g_tf_tab[N_TG + i] = make_float2(mu, 1.0f / (sg * sg));
    }
}

__global__ __launch_bounds__(THREADS)
void fused_loss_kernel(
    const float* __restrict__ TF_high_mu,
    const float* __restrict__ TF_high_sigma,
    const float* __restrict__ TG_mu,
    const float* __restrict__ TG_sigma,
    const float* __restrict__ TF_high_exp,
    const float* __restrict__ TG_exp,
    const float4* __restrict__ k_edge,
    const float4* __restrict__ alpha,
    const float4* __restrict__ cov,
    const float4* __restrict__ edge_y,
    const float4* __restrict__ edge_x,
    const int*   __restrict__ father_num,
    const int4*  __restrict__ idx_tf_tg,
    const int4*  __restrict__ idx_tf_high,
    const int4*  __restrict__ edge_tg_idx,
    const int4*  __restrict__ is_high,
    float* __restrict__ out)
{
    const float HALF_LOG2PI = 0.918938533204672742f;
    const int tid = blockIdx.x * THREADS + threadIdx.x;

    float acc = 0.0f;

    // ---- p/q terms (21k elems; negligible) ----
    if (tid < N_TG) {
        float mu = TG_mu[tid], sg = TG_sigma[tid], x = TG_exp[tid];
        float fn = (float)father_num[tid];
        float z = (x - mu) / sg;
        float lp = -0.5f * z * z - fast_logf(sg) - HALF_LOG2PI;
        acc += (fn - 1.0f) * lp;                           // -q
    }
    if (tid < N_TFH) {
        float mu = TF_high_mu[tid], sg = TF_high_sigma[tid], x = TF_high_exp[tid];
        float z = (x - mu) / sg;
        acc += 0.5f * z * z + fast_logf(sg) + HALF_LOG2PI; // -p
    }

    // ---- edge term: 4 edges per thread, one shot ----
    if (tid < NV) {
        // Streaming loads (evict-first: don't pollute cache holding the tables).
        float4 ke = __ldcs(k_edge + tid);
        float4 al = __ldcs(alpha  + tid);
        float4 cv = __ldcs(cov    + tid);
        float4 ey = __ldcs(edge_y + tid);
        float4 ex = __ldcs(edge_x + tid);
        int4  itg = __ldcs(idx_tf_tg   + tid);
        int4  ith = __ldcs(idx_tf_high + tid);
        int4  ieg = __ldcs(edge_tg_idx + tid);
        int4  ih  = __ldcs(is_high     + tid);

        const float* kef = &ke.x; const float* alf = &al.x;
        const float* cvf = &cv.x; const float* eyf = &ey.x;
        const float* exf = &ex.x;
        const int* itgf = &itg.x; const int* ithf = &ith.x;
        const int* iegf = &ieg.x; const int* ihf  = &ih.x;

        #pragma unroll
        for (int l = 0; l < 4; l++) {
            int tfi = ihf[l] ? (N_TG + ithf[l]) : itgf[l];
            float2 tf = g_tf_tab[tfi];       // (tf_mu, 1/tf_sig^2) — precomputed
            float2 tg = g_tg_tab[iegf[l]];   // (tg_mu, tg_sig^2)

            float iv  = tf.y;
            float loc = fmaf(kef[l] * cvf[l], (eyf[l] - tf.x) * iv, tg.x);
            loc = fmaxf(loc, 0.0f) + 0.01f;
            float var = fmaf(-alf[l] * alf[l], iv, tg.y);
            var = fmaxf(var, 0.0f) + 0.01f;

            float dx = exf[l] - loc;
            // -logprob = 0.5*(dx^2/var + log(var)) + 0.5*log(2pi)
            acc += fmaf(0.5f, fmaf(dx * dx, fast_rcp(var), fast_logf(var)),
                        HALF_LOG2PI);
        }
    }

    // ---- block reduction -> one atomic per block ----
    acc = warp_reduce(acc);
    __shared__ float warp_sums[THREADS / 32];
    int lane = threadIdx.x & 31, wid = threadIdx.x >> 5;
    if (lane == 0) warp_sums[wid] = acc;
    __syncthreads();
    if (wid == 0) {
        float v = (lane < THREADS / 32) ? warp_sums[lane] : 0.0f;
        v = warp_reduce(v);
        if (lane == 0) atomicAdd(out, v);
    }
}

extern "C" void kernel_launch(void* const* d_in, const int* in_sizes, int n_in,
                              void* d_out, int out_size) {
    const float* TF_high_mu    = (const float*)d_in[0];
    const float* TF_high_sigma = (const float*)d_in[1];
    const float* TG_mu         = (const float*)d_in[2];
    const float* TG_sigma      = (const float*)d_in[3];
    float* out = (float*)d_out;

    prep_kernel<<<(N_TG + 255) / 256, 256>>>(
        TF_high_mu, TF_high_sigma, TG_mu, TG_sigma, out);

    const int blocks = (NV + THREADS - 1) / THREADS;   // 3907
    fused_loss_kernel<<<blocks, THREADS>>>(
        TF_high_mu, TF_high_sigma, TG_mu, TG_sigma,
        (const float*)d_in[4], (const float*)d_in[5],
        (const float4*)d_in[6], (const float4*)d_in[7],
        (const float4*)d_in[8], (const float4*)d_in[9],
        (const float4*)d_in[10], (const int*)d_in[11],
        (const int4*)d_in[12], (const int4*)d_in[13],
        (const int4*)d_in[14], (const int4*)d_in[15],
        out);
}

// round 12
// speedup vs baseline: 1.2238x; 1.1231x over previous
#include <cuda_runtime.h>
#include <cuda_fp16.h>
#include <cstdint>
#include <cstddef>

#define N_TFH 1000
#define N_TG  20000
#define N_E   4000000
#define NV    (N_E / 4)          // 1,000,000 float4 groups
#define N_TAB (N_TG + N_TFH)     // 21,000 table entries
#define THREADS 512
#define BLOCKS  296              // 2 blocks per SM
#define SMEM_BYTES (N_TAB * 4)   // half2 table: 84,000 B

// Cross-block reduction state. Invariant: both are zero at every kernel
// entry (zero-initialized at load; the last block restores zero each call).
__device__ float    g_sum;
__device__ unsigned g_ticket;

__device__ __forceinline__ float warp_reduce(float v) {
    #pragma unroll
    for (int o = 16; o > 0; o >>= 1)
        v += __shfl_xor_sync(0xFFFFFFFFu, v, o);
    return v;
}

// FFMA-pipe reciprocal: bit-magic seed + 2 Newton iterations. No MUFU.
__device__ __forceinline__ float fast_rcp(float x) {
    float r = __int_as_float(0x7EF311C3 - __float_as_int(x));
    r = r * fmaf(-x, r, 2.0f);
    r = r * fmaf(-x, r, 2.0f);
    return r;
}

// FFMA-pipe natural log (njuffa-style), ~1e-7 rel. No MUFU.
__device__ __forceinline__ float fast_logf(float a) {
    int e = (__float_as_int(a) - 0x3f2aaaab) & 0xff800000;
    float m = __int_as_float(__float_as_int(a) - e);   // m in [2/3, 4/3)
    float i = (float)e * 1.19209290e-7f;
    float f = m - 1.0f;
    float s = f * f;
    float r = fmaf(0.230836749f, f, -0.279208571f);
    float t = fmaf(0.331826031f, f, -0.498910338f);
    r = fmaf(r, s, t);
    r = fmaf(r, s, f);
    r = fmaf(i, 0.693147182f, r);
    return r;
}

__global__ __launch_bounds__(THREADS, 2)
void fused_loss_kernel(
    const float* __restrict__ TF_high_mu,
    const float* __restrict__ TF_high_sigma,
    const float* __restrict__ TG_mu,
    const float* __restrict__ TG_sigma,
    const float* __restrict__ TF_high_exp,
    const float* __restrict__ TG_exp,
    const float4* __restrict__ k_edge,
    const float4* __restrict__ alpha,
    const float4* __restrict__ cov,
    const float4* __restrict__ edge_y,
    const float4* __restrict__ edge_x,
    const int*   __restrict__ father_num,
    const int4*  __restrict__ idx_tf_tg,
    const int4*  __restrict__ idx_tf_high,
    const int4*  __restrict__ edge_tg_idx,
    const int4*  __restrict__ is_high,
    float* __restrict__ out)
{
    extern __shared__ __half2 s_tab[];   // (mu, sigma^2) fp16, 84 KB
    const float HALF_LOG2PI = 0.918938533204672742f;
    const int tid = threadIdx.x;

    // ---- build fp16 (mu, sig^2) table from coalesced reads ----
    for (int i = tid; i < N_TG; i += THREADS) {
        float sg = TG_sigma[i];
        s_tab[i] = __floats2half2_rn(TG_mu[i], sg * sg);
    }
    for (int i = tid; i < N_TFH; i += THREADS) {
        float sg = TF_high_sigma[i];
        s_tab[N_TG + i] = __floats2half2_rn(TF_high_mu[i], sg * sg);
    }
    __syncthreads();

    float acc = 0.0f;
    const int gtid   = blockIdx.x * THREADS + tid;
    const int stride = BLOCKS * THREADS;

    // ---- p/q terms (21k elems; exact fp32 from global) ----
    if (gtid < N_TG) {
        float mu = TG_mu[gtid], sg = TG_sigma[gtid], x = TG_exp[gtid];
        float fn = (float)father_num[gtid];
        float z = (x - mu) / sg;
        float lp = -0.5f * z * z - fast_logf(sg) - HALF_LOG2PI;
        acc += (fn - 1.0f) * lp;                           // -q
    }
    if (gtid < N_TFH) {
        float mu = TF_high_mu[gtid], sg = TF_high_sigma[gtid], x = TF_high_exp[gtid];
        float z = (x - mu) / sg;
        acc += 0.5f * z * z + fast_logf(sg) + HALF_LOG2PI; // -p
    }

    // ---- edge term: grid-stride, MUFU-free, LDS.32 gathers ----
    for (int v = gtid; v < NV; v += stride) {
        float4 ke = __ldcs(k_edge + v);
        float4 al = __ldcs(alpha  + v);
        float4 cv = __ldcs(cov    + v);
        float4 ey = __ldcs(edge_y + v);
        float4 ex = __ldcs(edge_x + v);
        int4  itg = __ldcs(idx_tf_tg   + v);
        int4  ith = __ldcs(idx_tf_high + v);
        int4  ieg = __ldcs(edge_tg_idx + v);
        int4  ih  = __ldcs(is_high     + v);

        const float* kef = &ke.x; const float* alf = &al.x;
        const float* cvf = &cv.x; const float* eyf = &ey.x;
        const float* exf = &ex.x;
        const int* itgf = &itg.x; const int* ithf = &ith.x;
        const int* iegf = &ieg.x; const int* ihf  = &ih.x;

        #pragma unroll
        for (int l = 0; l < 4; l++) {
            int tfi = ihf[l] ? (N_TG + ithf[l]) : itgf[l];
            float2 tf = __half22float2(s_tab[tfi]);      // (tf_mu, tf_sig^2)
            float2 tg = __half22float2(s_tab[iegf[l]]);  // (tg_mu, tg_sig^2)

            float iv  = fast_rcp(tf.y);
            float loc = fmaf(kef[l] * cvf[l], (eyf[l] - tf.x) * iv, tg.x);
            loc = fmaxf(loc, 0.0f) + 0.01f;
            float var = fmaf(-alf[l] * alf[l], iv, tg.y);
            var = fmaxf(var, 0.0f) + 0.01f;

            float dx = exf[l] - loc;
            // -logprob = 0.5*(dx^2/var + log(var)) + 0.5*log(2pi)
            acc += fmaf(0.5f, fmaf(dx * dx, fast_rcp(var), fast_logf(var)),
                        HALF_LOG2PI);
        }
    }

    // ---- block reduction ----
    acc = warp_reduce(acc);
    __shared__ float warp_sums[THREADS / 32];
    int lane = tid & 31, wid = tid >> 5;
    if (lane == 0) warp_sums[wid] = acc;
    __syncthreads();
    if (wid == 0) {
        float v = (lane < THREADS / 32) ? warp_sums[lane] : 0.0f;
        v = warp_reduce(v);
        if (lane == 0) {
            // Cross-block: accumulate, then last block writes + resets.
            atomicAdd(&g_sum, v);
            __threadfence();
            unsigned t = atomicInc(&g_ticket, BLOCKS - 1);  // wraps to 0
            if (t == BLOCKS - 1) {
                out[0] = atomicExch(&g_sum, 0.0f);          // read + reset
            }
        }
    }
}

extern "C" void kernel_launch(void* const* d_in, const int* in_sizes, int n_in,
                              void* d_out, int out_size) {
    cudaFuncSetAttribute(fused_loss_kernel,
                         cudaFuncAttributeMaxDynamicSharedMemorySize, SMEM_BYTES);

    fused_loss_kernel<<<BLOCKS, THREADS, SMEM_BYTES>>>(
        (const float*)d_in[0], (const float*)d_in[1],
        (const float*)d_in[2], (const float*)d_in[3],
        (const float*)d_in[4], (const float*)d_in[5],
        (const float4*)d_in[6], (const float4*)d_in[7],
        (const float4*)d_in[8], (const float4*)d_in[9],
        (const float4*)d_in[10], (const int*)d_in[11],
        (const int4*)d_in[12], (const int4*)d_in[13],
        (const int4*)d_in[14], (const int4*)d_in[15],
        (float*)d_out);
}